// round 9
// baseline (speedup 1.0000x reference)
#include <cuda_runtime.h>
#include <stdint.h>

#define MAX_B     64
#define CAP       4096     // max recorded hits (expected ~5)
#define BM_WORDS  2048     // 65536-bit head bitmap (exact for nn<=65536)
#define NTHREADS  256
#define NBLOCKS   592
#define NFIX      64       // K2 grid

// Statically zero-initialized. Per-call protocol: K1's last block resets
// g_nrows/g_nfixups before writing them; K2 block 0 resets g_nhits/g_done1
// for the NEXT call (stream-ordered, so no race). Deterministic every replay.
__device__ int   g_nhits;
__device__ int   g_hit_b[CAP];
__device__ int   g_hit_t[CAP];
__device__ float g_hit_w[CAP];
__device__ int   g_nrows;             // # affected rows
__device__ int   g_row_id[MAX_B];
__device__ float g_row_inv[MAX_B];    // exact 1/S_b for affected rows
__device__ int   g_nfixups;
__device__ int   g_fixrow[CAP];       // index into affected-row list
__device__ int   g_fixcol[CAP];
__device__ float g_fixval[CAP];
__device__ int   g_done1;

__device__ __forceinline__ void record_hit(
    int eidx, int h,
    const unsigned int* __restrict__ sbm,
    const int* __restrict__ skeys,
    const int* __restrict__ etype,
    const int* __restrict__ tails,
    const float* __restrict__ w,
    int B, int nn)
{
    if (sbm[(h & 0xFFFF) >> 5] & (1u << (h & 31))) {
        if ((unsigned)h < (unsigned)nn) {
            int key  = (h << 9) | etype[eidx];
            int tail = tails[eidx];
            float wt = w[eidx];
            if ((unsigned)tail < (unsigned)nn) {
                for (int b = 0; b < B; b++) {
                    if (skeys[b] == key) {
                        int idx = atomicAdd(&g_nhits, 1);
                        if (idx < CAP) {
                            g_hit_b[idx] = b;
                            g_hit_t[idx] = tail;
                            g_hit_w[idx] = wt;
                        }
                    }
                }
            }
        }
    }
}

// ---------------------------------------------------------------------------
// K1: per-block [fill chunk with 1/nn] then [scan edge slice]; the two are
// independent so stores overlap the scan's loads. Last-finishing block
// aggregates hits into row/fixup lists. No block ever waits on another.
// ---------------------------------------------------------------------------
__global__ void __launch_bounds__(NTHREADS, 1)
k1_fill_scan(const int* __restrict__ heads,
             const int* __restrict__ etype,
             const int* __restrict__ tails,
             const float* __restrict__ w,
             const int* __restrict__ batch,
             float* __restrict__ out,
             int E, int B, int nn, int out_size)
{
    __shared__ unsigned int sbm[BM_WORDS];
    __shared__ int   skeys[MAX_B];
    __shared__ float sadj[MAX_B];
    __shared__ int   srow_of_b[MAX_B];
    __shared__ int   s_flag;

    const int tid = threadIdx.x;
    const int bid = blockIdx.x;
    const int nb  = gridDim.x;

    // ---- Phase A: per-block query keys + head bitmap ----
    for (int i = tid; i < BM_WORDS; i += NTHREADS) sbm[i] = 0u;
    __syncthreads();
    if (tid < B) {
        int h = batch[tid * 96 + 0];        // batch[b,0,0]
        int r = batch[tid * 96 + 2];        // batch[b,0,2]
        skeys[tid] = (h << 9) | r;          // num_rels < 512
        atomicOr(&sbm[(h & 0xFFFF) >> 5], 1u << (h & 31));
    }
    __syncthreads();

    // ---- Phase B: fill this block's output chunk with 1/nn ----
    const float inv0 = 1.0f / (float)nn;
    const long long lim = (long long)B * nn;
    const int n4 = out_size >> 2;
    {
        int perF = (n4 + nb - 1) / nb;
        int s4 = bid * perF;
        int e4 = s4 + perF; if (e4 > n4) e4 = n4;
        float4 v4 = make_float4(inv0, inv0, inv0, inv0);
        for (int i4 = s4 + tid; i4 < e4; i4 += NTHREADS) {
            long long pos = (long long)i4 << 2;
            if (pos + 3 < lim) {
                reinterpret_cast<float4*>(out)[i4] = v4;
            } else {
                #pragma unroll
                for (int c = 0; c < 4; c++)
                    out[pos + c] = (pos + c < lim) ? inv0 : 0.0f;  // ALPHA tail -> 0
            }
        }
        if (bid == nb - 1) {
            for (int p = (n4 << 2) + tid; p < out_size; p += NTHREADS)
                out[p] = ((long long)p < lim) ? inv0 : 0.0f;
        }
    }

    // ---- Phase C: scan this block's edge slice ----
    {
        const int4* h4 = reinterpret_cast<const int4*>(heads);
        int nQuads = E >> 2;
        int per = (nQuads + nb - 1) / nb;
        int s = bid * per;
        int e = s + per; if (e > nQuads) e = nQuads;
        for (int q = s + tid; q < e; q += NTHREADS) {
            int4 hh = h4[q];
            int eb = 4 * q;
            record_hit(eb + 0, hh.x, sbm, skeys, etype, tails, w, B, nn);
            record_hit(eb + 1, hh.y, sbm, skeys, etype, tails, w, B, nn);
            record_hit(eb + 2, hh.z, sbm, skeys, etype, tails, w, B, nn);
            record_hit(eb + 3, hh.w, sbm, skeys, etype, tails, w, B, nn);
        }
        if (bid == 0 && tid < (E & 3)) {
            int eidx = (nQuads << 2) + tid;
            record_hit(eidx, heads[eidx], sbm, skeys, etype, tails, w, B, nn);
        }
    }

    // ---- Phase D: last-finishing block aggregates (election, no waiting) ----
    __threadfence();
    __syncthreads();
    if (tid == 0) s_flag = (atomicAdd(&g_done1, 1) == nb - 1) ? 1 : 0;
    __syncthreads();
    if (!s_flag) return;

    for (int i = tid; i < B; i += NTHREADS) sadj[i] = 0.0f;
    if (tid == 0) { g_nrows = 0; g_nfixups = 0; }
    __syncthreads();
    int n = g_nhits; if (n > CAP) n = CAP;
    for (int i = tid; i < n; i += NTHREADS) {
        int b = g_hit_b[i], t = g_hit_t[i];
        float v = g_hit_w[i];
        bool owner = true;
        for (int j = 0; j < n; j++) {
            if (j == i) continue;
            if (g_hit_b[j] == b && g_hit_t[j] == t) {
                if (j < i) { owner = false; break; }
                v += g_hit_w[j];
            }
        }
        if (owner) atomicAdd(&sadj[b], __expf(v) - 1.0f);
    }
    __syncthreads();
    if (tid < B) {
        srow_of_b[tid] = -1;
        if (sadj[tid] != 0.0f) {
            int k = atomicAdd(&g_nrows, 1);
            g_row_id[k]  = tid;
            g_row_inv[k] = 1.0f / ((float)nn + sadj[tid]);
            srow_of_b[tid] = k;
        }
    }
    __syncthreads();
    for (int i = tid; i < n; i += NTHREADS) {
        int b = g_hit_b[i], t = g_hit_t[i];
        float v = g_hit_w[i];
        bool owner = true;
        for (int j = 0; j < n; j++) {
            if (j == i) continue;
            if (g_hit_b[j] == b && g_hit_t[j] == t) {
                if (j < i) { owner = false; break; }
                v += g_hit_w[j];
            }
        }
        if (owner) {
            int k = atomicAdd(&g_nfixups, 1);
            if (k < CAP) {
                g_fixrow[k] = srow_of_b[b];
                g_fixcol[k] = t;
                g_fixval[k] = __expf(v) / ((float)nn + sadj[b]);
            }
        }
    }
}

// ---------------------------------------------------------------------------
// K2: rewrite the <=5 affected rows exactly, apply hit fixups, reset state.
// Ordered after K1 by the stream — no cross-block synchronization anywhere.
// ---------------------------------------------------------------------------
__global__ void __launch_bounds__(NTHREADS, 1)
k2_fixup(float* __restrict__ out, int nn)
{
    const int tid = threadIdx.x;
    const int bid = blockIdx.x;

    if (bid == 0 && tid == 0) {        // reset for next replay (K1 is done)
        g_done1 = 0;
        g_nhits = 0;
    }

    int m = g_nrows;                   // affected rows (expected <= 5)
    if (m > 0) {
        long long total = (long long)m * nn;
        long long per = (total + NFIX - 1) / NFIX;
        long long lo = (long long)bid * per;
        long long hi = lo + per; if (hi > total) hi = total;
        for (long long v = lo + tid; v < hi; v += NTHREADS) {
            int ri = (int)(v / nn);
            int col = (int)(v - (long long)ri * nn);
            out[(long long)g_row_id[ri] * nn + col] = g_row_inv[ri];
        }
        __syncthreads();
        int nf = g_nfixups; if (nf > CAP) nf = CAP;
        for (int i = tid; i < nf; i += NTHREADS) {
            long long v = (long long)g_fixrow[i] * nn + g_fixcol[i];
            if (v >= lo && v < hi)
                out[(long long)g_row_id[g_fixrow[i]] * nn + g_fixcol[i]] = g_fixval[i];
        }
    }
}

extern "C" void kernel_launch(void* const* d_in, const int* in_sizes, int n_in,
                              void* d_out, int out_size) {
    // ---- Identify inputs by SIZE SIGNATURE (ordering-invariant) ----
    int iEI = 0, maxSz = 0;
    for (int i = 0; i < n_in; i++)
        if (in_sizes[i] > maxSz) { maxSz = in_sizes[i]; iEI = i; }
    int E = maxSz / 2;

    int iB = -1, iT = -1, iW = -1;
    for (int i = 0; i < n_in; i++) {
        if (i == iEI) continue;
        int s = in_sizes[i];
        if (s == E)                               { if (iT < 0) iT = i; else iW = i; }
        else if (s > 1 && (s % 96) == 0 && iB < 0) iB = i;
    }

    const int*   edge_index = (const int*)d_in[iEI];
    const int*   edge_type  = (const int*)d_in[iT];
    const int*   batch      = (const int*)d_in[iB];
    const float* edge_w     = (const float*)d_in[iW];

    int B  = in_sizes[iB] / 96;       // 64
    if (B > MAX_B) B = MAX_B;
    int nn = out_size / B;            // 50000
    const int* heads = edge_index;
    const int* tails = edge_index + E;

    k1_fill_scan<<<NBLOCKS, NTHREADS>>>(heads, edge_type, tails, edge_w,
                                        batch, (float*)d_out,
                                        E, B, nn, out_size);
    k2_fixup<<<NFIX, NTHREADS>>>((float*)d_out, nn);
}

// round 10
// speedup vs baseline: 1.0211x; 1.0211x over previous
#include <cuda_runtime.h>
#include <stdint.h>

#define MAX_B     64
#define CAP       4096     // max recorded hits (expected ~5)
#define BM_WORDS  2048     // 65536-bit head bitmap (exact for nn<=65536)
#define NTHREADS  256
#define NBLOCKS   592      // 4 blocks/SM x 148 SMs — all co-resident

// Statically zero-initialized; elected last block restores zero state at the
// end of every launch, so each graph replay starts clean.
__device__ int          g_nhits;
__device__ int          g_hit_b[CAP];
__device__ int          g_hit_t[CAP];
__device__ float        g_hit_w[CAP];
__device__ int          g_nrows;
__device__ int          g_row_id[MAX_B];
__device__ float        g_row_inv[MAX_B];     // exact 1/S_b for affected rows
__device__ int          g_nfixups;
__device__ long long    g_fix_pos[CAP];       // absolute output position
__device__ float        g_fix_val[CAP];
__device__ int          g_done1, g_done2;
__device__ volatile int g_phase;

__device__ __forceinline__ void record_hit(
    int eidx, int h,
    const unsigned int* __restrict__ sbm,
    const int* __restrict__ skeys,
    const int* __restrict__ etype,
    const int* __restrict__ tails,
    const float* __restrict__ w,
    int B, int nn)
{
    if (sbm[(h & 0xFFFF) >> 5] & (1u << (h & 31))) {
        if ((unsigned)h < (unsigned)nn) {
            int key  = (h << 9) | etype[eidx];
            int tail = tails[eidx];
            float wt = w[eidx];
            if ((unsigned)tail < (unsigned)nn) {
                for (int b = 0; b < B; b++) {
                    if (skeys[b] == key) {
                        int idx = atomicAdd(&g_nhits, 1);
                        if (idx < CAP) {
                            g_hit_b[idx] = b;
                            g_hit_t[idx] = tail;
                            g_hit_w[idx] = wt;
                        }
                    }
                }
            }
        }
    }
}

__global__ void __launch_bounds__(NTHREADS, 1)
fused_kernel(const int* __restrict__ heads,
             const int* __restrict__ etype,
             const int* __restrict__ tails,
             const float* __restrict__ w,
             const int* __restrict__ batch,
             float* __restrict__ out,
             int E, int B, int nn, int out_size)
{
    __shared__ unsigned int sbm[BM_WORDS];
    __shared__ int   skeys[MAX_B];
    __shared__ float sadj[MAX_B];
    __shared__ int   srow_of_b[MAX_B];
    __shared__ int   s_flag;

    const int tid = threadIdx.x;
    const int bid = blockIdx.x;
    const int nb  = gridDim.x;

    // ---- Phase A: per-block query keys + head bitmap ----
    for (int i = tid; i < BM_WORDS; i += NTHREADS) sbm[i] = 0u;
    __syncthreads();
    if (tid < B) {
        int h = batch[tid * 96 + 0];        // batch[b,0,0]
        int r = batch[tid * 96 + 2];        // batch[b,0,2]
        skeys[tid] = (h << 9) | r;          // num_rels < 512
        atomicOr(&sbm[(h & 0xFFFF) >> 5], 1u << (h & 31));
    }
    __syncthreads();

    // ---- Phase B: fill own chunk with 1/nn (exact for unaffected rows);
    //      starts immediately, independent of the scan ----
    const float inv0 = 1.0f / (float)nn;
    const long long lim = (long long)B * nn;
    const int n4 = out_size >> 2;
    const int perF = (n4 + nb - 1) / nb;
    const int s4 = bid * perF;
    int e4t = s4 + perF; if (e4t > n4) e4t = n4;
    const int e4 = e4t;
    {
        float4 v4 = make_float4(inv0, inv0, inv0, inv0);
        for (int i4 = s4 + tid; i4 < e4; i4 += NTHREADS) {
            long long pos = (long long)i4 << 2;
            if (pos + 3 < lim) {
                reinterpret_cast<float4*>(out)[i4] = v4;
            } else {
                #pragma unroll
                for (int c = 0; c < 4; c++)
                    out[pos + c] = (pos + c < lim) ? inv0 : 0.0f;  // ALPHA tail -> 0
            }
        }
        if (bid == nb - 1) {
            for (int p = (n4 << 2) + tid; p < out_size; p += NTHREADS)
                out[p] = ((long long)p < lim) ? inv0 : 0.0f;
        }
    }

    // ---- Phase C: scan own edge slice ----
    {
        const int4* h4 = reinterpret_cast<const int4*>(heads);
        int nQuads = E >> 2;
        int per = (nQuads + nb - 1) / nb;
        int s = bid * per;
        int e = s + per; if (e > nQuads) e = nQuads;
        for (int q = s + tid; q < e; q += NTHREADS) {
            int4 hh = h4[q];
            int eb = 4 * q;
            record_hit(eb + 0, hh.x, sbm, skeys, etype, tails, w, B, nn);
            record_hit(eb + 1, hh.y, sbm, skeys, etype, tails, w, B, nn);
            record_hit(eb + 2, hh.z, sbm, skeys, etype, tails, w, B, nn);
            record_hit(eb + 3, hh.w, sbm, skeys, etype, tails, w, B, nn);
        }
        if (bid == 0 && tid < (E & 3)) {
            int eidx = (nQuads << 2) + tid;
            record_hit(eidx, heads[eidx], sbm, skeys, etype, tails, w, B, nn);
        }
    }

    // ---- Phase D: done-counter election; last block aggregates ----
    __threadfence();
    __syncthreads();
    if (tid == 0) s_flag = (atomicAdd(&g_done1, 1) == nb - 1) ? 1 : 0;
    __syncthreads();

    if (s_flag) {
        for (int i = tid; i < B; i += NTHREADS) sadj[i] = 0.0f;
        if (tid == 0) { g_nrows = 0; g_nfixups = 0; }
        __syncthreads();
        int n = g_nhits; if (n > CAP) n = CAP;
        for (int i = tid; i < n; i += NTHREADS) {
            int b = g_hit_b[i], t = g_hit_t[i];
            float v = g_hit_w[i];
            bool owner = true;
            for (int j = 0; j < n; j++) {
                if (j == i) continue;
                if (g_hit_b[j] == b && g_hit_t[j] == t) {
                    if (j < i) { owner = false; break; }
                    v += g_hit_w[j];
                }
            }
            if (owner) atomicAdd(&sadj[b], __expf(v) - 1.0f);
        }
        __syncthreads();
        if (tid < B) {
            srow_of_b[tid] = -1;
            if (sadj[tid] != 0.0f) {
                int k = atomicAdd(&g_nrows, 1);
                g_row_id[k]  = tid;
                g_row_inv[k] = 1.0f / ((float)nn + sadj[tid]);
                srow_of_b[tid] = k;
            }
        }
        __syncthreads();
        for (int i = tid; i < n; i += NTHREADS) {
            int b = g_hit_b[i], t = g_hit_t[i];
            float v = g_hit_w[i];
            bool owner = true;
            for (int j = 0; j < n; j++) {
                if (j == i) continue;
                if (g_hit_b[j] == b && g_hit_t[j] == t) {
                    if (j < i) { owner = false; break; }
                    v += g_hit_w[j];
                }
            }
            if (owner) {
                int k = atomicAdd(&g_nfixups, 1);
                if (k < CAP) {
                    g_fix_pos[k] = (long long)b * nn + t;
                    g_fix_val[k] = __expf(v) / ((float)nn + sadj[b]);
                }
            }
        }
        __syncthreads();
        __threadfence();
        if (tid == 0) g_phase = 1;
    } else {
        if (tid == 0) { while (g_phase == 0) __nanosleep(64); }
        __syncthreads();
        __threadfence();
    }

    // ---- Phase E: each block fixes ONLY its own chunk (disjoint, tiny) ----
    {
        const long long clo = (long long)s4 << 2;
        const long long chi = (bid == nb - 1) ? (long long)out_size
                                              : ((long long)e4 << 2);
        int m = g_nrows;                    // affected rows (expected <= 5)
        for (int ri = 0; ri < m; ri++) {
            long long rlo = (long long)g_row_id[ri] * nn;
            long long rhi = rlo + nn;
            long long lo = rlo > clo ? rlo : clo;
            long long hi = rhi < chi ? rhi : chi;
            float rv = g_row_inv[ri];
            for (long long p = lo + tid; p < hi; p += NTHREADS)
                out[p] = rv;
        }
        __syncthreads();                    // row-rewrite before point fixups
        int nf = g_nfixups; if (nf > CAP) nf = CAP;
        for (int i = tid; i < nf; i += NTHREADS) {
            long long p = g_fix_pos[i];
            if (p >= clo && p < chi) out[p] = g_fix_val[i];
        }
    }

    // ---- Phase F: elected last block resets state for next replay ----
    __threadfence();
    __syncthreads();
    if (tid == 0) {
        if (atomicAdd(&g_done2, 1) == nb - 1) {
            g_done2 = 0;
            g_done1 = 0;
            g_nhits = 0;
            g_phase = 0;
        }
    }
}

extern "C" void kernel_launch(void* const* d_in, const int* in_sizes, int n_in,
                              void* d_out, int out_size) {
    // ---- Identify inputs by SIZE SIGNATURE (ordering-invariant) ----
    int iEI = 0, maxSz = 0;
    for (int i = 0; i < n_in; i++)
        if (in_sizes[i] > maxSz) { maxSz = in_sizes[i]; iEI = i; }
    int E = maxSz / 2;

    int iB = -1, iT = -1, iW = -1;
    for (int i = 0; i < n_in; i++) {
        if (i == iEI) continue;
        int s = in_sizes[i];
        if (s == E)                               { if (iT < 0) iT = i; else iW = i; }
        else if (s > 1 && (s % 96) == 0 && iB < 0) iB = i;
    }

    const int*   edge_index = (const int*)d_in[iEI];
    const int*   edge_type  = (const int*)d_in[iT];
    const int*   batch      = (const int*)d_in[iB];
    const float* edge_w     = (const float*)d_in[iW];

    int B  = in_sizes[iB] / 96;       // 64
    if (B > MAX_B) B = MAX_B;
    int nn = out_size / B;            // 50000
    const int* heads = edge_index;
    const int* tails = edge_index + E;

    fused_kernel<<<NBLOCKS, NTHREADS>>>(heads, edge_type, tails, edge_w,
                                        batch, (float*)d_out,
                                        E, B, nn, out_size);
}

// round 11
// speedup vs baseline: 1.5300x; 1.4983x over previous
#include <cuda_runtime.h>
#include <stdint.h>

#define MAX_B     64
#define CAP       4096     // max recorded hits (expected ~5)
#define BM_WORDS  2048     // 65536-bit head bitmap (exact for nn<=65536)
#define NT        256

// Statically zero-initialized. K2 resets g_nhits at its end each call
// (stream-ordered before the next replay's K1), so every replay starts clean.
__device__ int       g_nhits;
__device__ int       g_hit_b[CAP];
__device__ int       g_hit_t[CAP];
__device__ float     g_hit_w[CAP];
__device__ float     g_rowval[MAX_B];     // exact 1/S_b for EVERY row
__device__ int       g_nfix;
__device__ long long g_fix_pos[CAP];      // absolute output position
__device__ float     g_fix_val[CAP];

__device__ __forceinline__ void record_hit(
    int eidx, int h,
    const unsigned int* __restrict__ sbm,
    const int* __restrict__ skeys,
    const int* __restrict__ etype,
    const int* __restrict__ tails,
    const float* __restrict__ w,
    int B, int nn)
{
    if (sbm[(h & 0xFFFF) >> 5] & (1u << (h & 31))) {
        if ((unsigned)h < (unsigned)nn) {
            int key  = (h << 9) | etype[eidx];
            int tail = tails[eidx];
            float wt = w[eidx];
            if ((unsigned)tail < (unsigned)nn) {
                for (int b = 0; b < B; b++) {
                    if (skeys[b] == key) {
                        int idx = atomicAdd(&g_nhits, 1);
                        if (idx < CAP) {
                            g_hit_b[idx] = b;
                            g_hit_t[idx] = tail;
                            g_hit_w[idx] = wt;
                        }
                    }
                }
            }
        }
    }
}

// ---------------------------------------------------------------------------
// K1: pure streaming scan. One int4 of heads per thread; per-block smem
// bitmap prefilter; hits appended to global list. No cross-block sync.
// ---------------------------------------------------------------------------
__global__ void __launch_bounds__(NT, 1)
k1_scan(const int* __restrict__ heads,
        const int* __restrict__ etype,
        const int* __restrict__ tails,
        const float* __restrict__ w,
        const int* __restrict__ batch,
        int E, int B, int nn)
{
    __shared__ unsigned int sbm[BM_WORDS];
    __shared__ int skeys[MAX_B];
    const int tid = threadIdx.x;

    for (int i = tid; i < BM_WORDS; i += NT) sbm[i] = 0u;
    __syncthreads();
    if (tid < B) {
        int h = batch[tid * 96 + 0];        // batch[b,0,0]
        int r = batch[tid * 96 + 2];        // batch[b,0,2]
        skeys[tid] = (h << 9) | r;          // num_rels < 512
        atomicOr(&sbm[(h & 0xFFFF) >> 5], 1u << (h & 31));
    }
    __syncthreads();

    const int4* h4 = reinterpret_cast<const int4*>(heads);
    int nQuads = E >> 2;
    int q = blockIdx.x * NT + tid;
    if (q < nQuads) {
        int4 hh = h4[q];
        int eb = 4 * q;
        record_hit(eb + 0, hh.x, sbm, skeys, etype, tails, w, B, nn);
        record_hit(eb + 1, hh.y, sbm, skeys, etype, tails, w, B, nn);
        record_hit(eb + 2, hh.z, sbm, skeys, etype, tails, w, B, nn);
        record_hit(eb + 3, hh.w, sbm, skeys, etype, tails, w, B, nn);
    }
    if (blockIdx.x == 0 && tid < (E & 3)) {
        int eidx = (nQuads << 2) + tid;
        record_hit(eidx, heads[eidx], sbm, skeys, etype, tails, w, B, nn);
    }
}

// ---------------------------------------------------------------------------
// K2: single tiny block. Dedupe hits, compute 1/S_b for every row, emit
// point-fixup list, reset the hit counter for the next graph replay.
// Kernel boundary after K1 guarantees visibility of the hit list.
// ---------------------------------------------------------------------------
__global__ void __launch_bounds__(NT, 1)
k2_aggregate(int B, int nn)
{
    __shared__ float sadj[MAX_B];
    __shared__ int   snf;
    const int tid = threadIdx.x;

    for (int i = tid; i < MAX_B; i += NT) sadj[i] = 0.0f;
    if (tid == 0) snf = 0;
    __syncthreads();

    int n = g_nhits; if (n > CAP) n = CAP;
    for (int i = tid; i < n; i += NT) {
        int b = g_hit_b[i], t = g_hit_t[i];
        float v = g_hit_w[i];
        bool owner = true;
        for (int j = 0; j < n; j++) {
            if (j == i) continue;
            if (g_hit_b[j] == b && g_hit_t[j] == t) {
                if (j < i) { owner = false; break; }
                v += g_hit_w[j];
            }
        }
        if (owner) atomicAdd(&sadj[b], __expf(v) - 1.0f);
    }
    __syncthreads();

    if (tid < B) g_rowval[tid] = 1.0f / ((float)nn + sadj[tid]);
    __syncthreads();

    for (int i = tid; i < n; i += NT) {
        int b = g_hit_b[i], t = g_hit_t[i];
        float v = g_hit_w[i];
        bool owner = true;
        for (int j = 0; j < n; j++) {
            if (j == i) continue;
            if (g_hit_b[j] == b && g_hit_t[j] == t) {
                if (j < i) { owner = false; break; }
                v += g_hit_w[j];
            }
        }
        if (owner) {
            int k = atomicAdd(&snf, 1);
            if (k < CAP) {
                g_fix_pos[k] = (long long)b * nn + t;
                g_fix_val[k] = __expf(v) / ((float)nn + sadj[b]);
            }
        }
    }
    __syncthreads();
    if (tid == 0) {
        g_nfix  = (snf > CAP) ? CAP : snf;
        g_nhits = 0;                         // clean state for next replay
    }
}

// ---------------------------------------------------------------------------
// K3: pure streaming fill. Each block writes a disjoint 4 KB chunk (2 float4
// per thread) using the smem row-value table, then applies the <=5 point
// fixups that fall inside its own chunk (ordered by __syncthreads).
// ---------------------------------------------------------------------------
__global__ void __launch_bounds__(NT, 1)
k3_fill(float* __restrict__ out, int B, int nn, int out_size)
{
    __shared__ float srow[MAX_B];
    const int tid = threadIdx.x;
    if (tid < B) srow[tid] = g_rowval[tid];
    __syncthreads();

    const long long lim = (long long)B * nn;
    const int n4 = out_size >> 2;
    const int base = blockIdx.x * (NT * 2);

    if ((nn & 3) == 0) {
        int nn4 = nn >> 2;
        #pragma unroll
        for (int j = 0; j < 2; j++) {
            int i4 = base + j * NT + tid;
            if (i4 < n4) {
                int r = i4 / nn4;
                float v = (r < B) ? srow[r] : 0.0f;
                reinterpret_cast<float4*>(out)[i4] = make_float4(v, v, v, v);
            }
        }
    } else {
        #pragma unroll
        for (int j = 0; j < 2; j++) {
            int i4 = base + j * NT + tid;
            if (i4 < n4) {
                long long pos = (long long)i4 << 2;
                #pragma unroll
                for (int c = 0; c < 4; c++) {
                    long long p = pos + c;
                    out[p] = (p < lim) ? srow[(int)(p / nn)] : 0.0f;
                }
            }
        }
    }
    // scalar tail (out_size % 4) — last block, before its syncthreads
    const bool lastBlk = (blockIdx.x == gridDim.x - 1);
    if (lastBlk) {
        for (int p = (n4 << 2) + tid; p < out_size; p += NT)
            out[p] = ((long long)p < lim) ? srow[(int)((long long)p / nn)] : 0.0f;
    }
    __syncthreads();

    // point fixups inside this block's chunk (disjoint across blocks)
    {
        long long clo = (long long)base << 2;
        long long chi = lastBlk ? (long long)out_size
                                : ((long long)(base + NT * 2) << 2);
        if (chi > out_size) chi = out_size;
        int nf = g_nfix; if (nf > CAP) nf = CAP;
        for (int i = tid; i < nf; i += NT) {
            long long p = g_fix_pos[i];
            if (p >= clo && p < chi) out[p] = g_fix_val[i];
        }
    }
}

extern "C" void kernel_launch(void* const* d_in, const int* in_sizes, int n_in,
                              void* d_out, int out_size) {
    // ---- Identify inputs by SIZE SIGNATURE (ordering-invariant) ----
    int iEI = 0, maxSz = 0;
    for (int i = 0; i < n_in; i++)
        if (in_sizes[i] > maxSz) { maxSz = in_sizes[i]; iEI = i; }
    int E = maxSz / 2;

    int iB = -1, iT = -1, iW = -1;
    for (int i = 0; i < n_in; i++) {
        if (i == iEI) continue;
        int s = in_sizes[i];
        if (s == E)                               { if (iT < 0) iT = i; else iW = i; }
        else if (s > 1 && (s % 96) == 0 && iB < 0) iB = i;
    }

    const int*   edge_index = (const int*)d_in[iEI];
    const int*   edge_type  = (const int*)d_in[iT];
    const int*   batch      = (const int*)d_in[iB];
    const float* edge_w     = (const float*)d_in[iW];

    int B  = in_sizes[iB] / 96;       // 64
    if (B > MAX_B) B = MAX_B;
    int nn = out_size / B;            // 50000
    const int* heads = edge_index;
    const int* tails = edge_index + E;

    // K1: streaming scan (1 int4 per thread)
    int nQuads = E >> 2;
    int g1 = (nQuads + NT - 1) / NT;
    if (g1 < 1) g1 = 1;
    k1_scan<<<g1, NT>>>(heads, edge_type, tails, edge_w, batch, E, B, nn);

    // K2: tiny aggregation
    k2_aggregate<<<1, NT>>>(B, nn);

    // K3: streaming fill + in-chunk fixups (2 float4 per thread)
    int n4 = out_size >> 2;
    int g3 = (n4 + NT * 2 - 1) / (NT * 2);
    if (g3 < 1) g3 = 1;
    k3_fill<<<g3, NT>>>((float*)d_out, B, nn, out_size);
}